// round 3
// baseline (speedup 1.0000x reference)
#include <cuda_runtime.h>
#include <math.h>

#define BD 512
#define MD 32768
#define NPREDD 20
#define FUTD 12
#define NROWS (BD*NPREDD)
#define NSLICE 9
#define SLICE_LEN 3641

__device__ float g_state[BD*48];
__device__ float g_q[BD*48];
__device__ float g_K[MD*48];
__device__ float g_V[MD*48];
__device__ float g_part[NSLICE*BD*52];
__device__ float g_pred[NROWS*48];
__device__ float g_wTih[96*288];
__device__ float g_wThh[96*288];

__device__ __forceinline__ float sg_(float x){ return 1.f/(1.f+__expf(-x)); }

// ---------- encoder: conv1d(2,48,3,p=1)+ReLU, GRU(48) x8, q0 ----------
__global__ void enc_kernel(const float* __restrict__ past,
    const float* __restrict__ cw, const float* __restrict__ cb,
    const float* __restrict__ wih, const float* __restrict__ whh,
    const float* __restrict__ bih, const float* __restrict__ bhh,
    const float* __restrict__ Wq, const float* __restrict__ bq)
{
    __shared__ float se[8][48];
    __shared__ float sh[48];
    __shared__ float sgi[144], sgh[144];
    int b = blockIdx.x, tid = threadIdx.x;
    for (int idx = tid; idx < 8*48; idx += 144) {
        int t = idx/48, c = idx%48;
        float s = cb[c];
        #pragma unroll
        for (int k = 0; k < 3; k++) {
            int tt = t + k - 1;
            if (tt >= 0 && tt < 8) {
                s = fmaf(cw[c*6+k],   past[b*16+tt*2+0], s);
                s = fmaf(cw[c*6+3+k], past[b*16+tt*2+1], s);
            }
        }
        se[t][c] = fmaxf(s, 0.f);
    }
    if (tid < 48) sh[tid] = 0.f;
    __syncthreads();
    for (int t = 0; t < 8; t++) {
        float gi = bih[tid], gh = bhh[tid];
        const float* wi = wih + tid*48;
        const float* wh = whh + tid*48;
        #pragma unroll 8
        for (int d = 0; d < 48; d++) {
            gi = fmaf(se[t][d], wi[d], gi);
            gh = fmaf(sh[d],    wh[d], gh);
        }
        sgi[tid] = gi; sgh[tid] = gh;
        __syncthreads();
        float hn = 0.f;
        if (tid < 48) {
            float r = sg_(sgi[tid]    + sgh[tid]);
            float z = sg_(sgi[48+tid] + sgh[48+tid]);
            float n = tanhf(sgi[96+tid] + r*sgh[96+tid]);
            hn = (1.f-z)*n + z*sh[tid];
        }
        __syncthreads();
        if (tid < 48) sh[tid] = hn;
        __syncthreads();
    }
    if (tid < 48) {
        g_state[b*48+tid] = sh[tid];
        float q = bq[tid];
        const float* w = Wq + tid*48;
        #pragma unroll 8
        for (int d = 0; d < 48; d++) q = fmaf(sh[d], w[d], q);
        g_q[b*48+tid] = q;
    }
}

// ---------- K/V projection ----------
__global__ void kv_kernel(const float* __restrict__ mp, const float* __restrict__ mf,
    const float* __restrict__ Wk, const float* __restrict__ bk,
    const float* __restrict__ Wv, const float* __restrict__ bv)
{
    int idx = blockIdx.x*blockDim.x + threadIdx.x;
    if (idx >= MD*48) return;
    int m = idx/48, j = idx - m*48;
    const float* rp = mp + m*48;
    const float* rf = mf + m*48;
    const float* wk = Wk + j*48;
    const float* wv = Wv + j*48;
    float sk = bk[j], sv = bv[j];
    #pragma unroll 8
    for (int d = 0; d < 48; d++) {
        sk = fmaf(rp[d], wk[d], sk);
        sv = fmaf(rf[d], wv[d], sv);
    }
    g_K[idx] = sk;
    g_V[idx] = sv;
}

// ---------- decoder weight transpose ----------
__global__ void wt_kernel(const float* __restrict__ wih, const float* __restrict__ whh)
{
    int i = blockIdx.x*blockDim.x + threadIdx.x;
    if (i < 288*96) {
        int j = i/96, k = i - j*96;
        g_wTih[k*288+j] = wih[i];
        g_wThh[k*288+j] = whh[i];
    }
}

// ---------- attention partials (flash, split-M) ----------
__global__ void __launch_bounds__(512,1) attn_kernel()
{
    __shared__ float sK[64*52];
    __shared__ float sV[64*52];
    __shared__ float sq[32*48];
    int tid = threadIdx.x, lane = tid & 31, w = tid >> 5;
    int qbase = blockIdx.y*32;
    int m_start = blockIdx.x*SLICE_LEN;
    int m_end = min(MD, m_start + SLICE_LEN);

    for (int i = tid; i < 32*48; i += 512) sq[i] = g_q[qbase*48 + i];

    float acc0[48], acc1[48];
    #pragma unroll
    for (int d = 0; d < 48; d++) { acc0[d] = 0.f; acc1[d] = 0.f; }
    float rm0 = -1e30f, rm1 = -1e30f, sum0 = 0.f, sum1 = 0.f;
    int q0 = w*2, q1 = w*2 + 1;
    const float4* q4a = (const float4*)sq + q0*12;
    const float4* q4b = (const float4*)sq + q1*12;
    const float4* k4a = (const float4*)sK + lane*13;
    const float4* k4b = (const float4*)sK + (lane+32)*13;
    const float4* v4a = (const float4*)sV + lane*13;
    const float4* v4b = (const float4*)sV + (lane+32)*13;

    for (int m0 = m_start; m0 < m_end; m0 += 64) {
        int rows = min(64, m_end - m0);
        __syncthreads();
        {
            const float4* gK4 = (const float4*)g_K + (long)m0*12;
            const float4* gV4 = (const float4*)g_V + (long)m0*12;
            for (int i = tid; i < rows*12; i += 512) {
                int r = i/12, d4 = i - r*12;
                ((float4*)sK)[r*13 + d4] = gK4[i];
                ((float4*)sV)[r*13 + d4] = gV4[i];
            }
        }
        __syncthreads();

        float s00 = 0.f, s01 = 0.f, s10 = 0.f, s11 = 0.f;
        #pragma unroll
        for (int d4 = 0; d4 < 12; d4++) {
            float4 ka = k4a[d4], kb = k4b[d4];
            float4 qa = q4a[d4], qb = q4b[d4];
            s00 = fmaf(qa.x,ka.x,s00); s00 = fmaf(qa.y,ka.y,s00);
            s00 = fmaf(qa.z,ka.z,s00); s00 = fmaf(qa.w,ka.w,s00);
            s01 = fmaf(qa.x,kb.x,s01); s01 = fmaf(qa.y,kb.y,s01);
            s01 = fmaf(qa.z,kb.z,s01); s01 = fmaf(qa.w,kb.w,s01);
            s10 = fmaf(qb.x,ka.x,s10); s10 = fmaf(qb.y,ka.y,s10);
            s10 = fmaf(qb.z,ka.z,s10); s10 = fmaf(qb.w,ka.w,s10);
            s11 = fmaf(qb.x,kb.x,s11); s11 = fmaf(qb.y,kb.y,s11);
            s11 = fmaf(qb.z,kb.z,s11); s11 = fmaf(qb.w,kb.w,s11);
        }
        if (lane      >= rows) { s00 = -1e30f; s10 = -1e30f; }
        if (lane + 32 >= rows) { s01 = -1e30f; s11 = -1e30f; }

        float nm0 = fmaxf(rm0, fmaxf(s00, s01));
        float f0 = __expf(rm0 - nm0);
        float p00 = __expf(s00 - nm0), p01 = __expf(s01 - nm0);
        sum0 = fmaf(sum0, f0, p00 + p01); rm0 = nm0;
        float nm1 = fmaxf(rm1, fmaxf(s10, s11));
        float f1 = __expf(rm1 - nm1);
        float p10 = __expf(s10 - nm1), p11 = __expf(s11 - nm1);
        sum1 = fmaf(sum1, f1, p10 + p11); rm1 = nm1;

        #pragma unroll
        for (int d4 = 0; d4 < 12; d4++) {
            float4 va = v4a[d4], vb = v4b[d4];
            int d = d4*4;
            acc0[d+0] = fmaf(acc0[d+0], f0, fmaf(p00, va.x, p01*vb.x));
            acc0[d+1] = fmaf(acc0[d+1], f0, fmaf(p00, va.y, p01*vb.y));
            acc0[d+2] = fmaf(acc0[d+2], f0, fmaf(p00, va.z, p01*vb.z));
            acc0[d+3] = fmaf(acc0[d+3], f0, fmaf(p00, va.w, p01*vb.w));
            acc1[d+0] = fmaf(acc1[d+0], f1, fmaf(p10, va.x, p11*vb.x));
            acc1[d+1] = fmaf(acc1[d+1], f1, fmaf(p10, va.y, p11*vb.y));
            acc1[d+2] = fmaf(acc1[d+2], f1, fmaf(p10, va.z, p11*vb.z));
            acc1[d+3] = fmaf(acc1[d+3], f1, fmaf(p10, va.w, p11*vb.w));
        }
    }

    #pragma unroll
    for (int off = 16; off > 0; off >>= 1) {
        float om0 = __shfl_xor_sync(0xffffffffu, rm0, off);
        float os0 = __shfl_xor_sync(0xffffffffu, sum0, off);
        float nm0 = fmaxf(rm0, om0);
        float a0 = __expf(rm0 - nm0), b0 = __expf(om0 - nm0);
        sum0 = fmaf(sum0, a0, os0*b0);
        float om1 = __shfl_xor_sync(0xffffffffu, rm1, off);
        float os1 = __shfl_xor_sync(0xffffffffu, sum1, off);
        float nm1 = fmaxf(rm1, om1);
        float a1 = __expf(rm1 - nm1), b1 = __expf(om1 - nm1);
        sum1 = fmaf(sum1, a1, os1*b1);
        #pragma unroll
        for (int d = 0; d < 48; d++) {
            float oa0 = __shfl_xor_sync(0xffffffffu, acc0[d], off);
            acc0[d] = fmaf(acc0[d], a0, oa0*b0);
            float oa1 = __shfl_xor_sync(0xffffffffu, acc1[d], off);
            acc1[d] = fmaf(acc1[d], a1, oa1*b1);
        }
        rm0 = nm0; rm1 = nm1;
    }

    long s = blockIdx.x;
    if (lane == 0) {
        float* P = g_part + (s*BD + (qbase+q0))*52;
        #pragma unroll
        for (int d = 0; d < 48; d++) P[d] = acc0[d];
        P[48] = rm0; P[49] = sum0;
    }
    if (lane == 1) {
        float* P = g_part + (s*BD + (qbase+q1))*52;
        #pragma unroll
        for (int d = 0; d < 48; d++) P[d] = acc1[d];
        P[48] = rm1; P[49] = sum1;
    }
}

// ---------- combine partials + emit pred + next q ----------
__global__ void combine_kernel(const float* __restrict__ Wq, const float* __restrict__ bq,
                               int iter)
{
    __shared__ float sc[48];
    int q = blockIdx.x, d = threadIdx.x;
    float gm = -1e30f;
    #pragma unroll
    for (int s = 0; s < NSLICE; s++)
        gm = fmaxf(gm, g_part[((long)s*BD+q)*52 + 48]);
    float tot = 0.f, av = 0.f;
    #pragma unroll
    for (int s = 0; s < NSLICE; s++) {
        const float* P = g_part + ((long)s*BD+q)*52;
        float sc2 = __expf(P[48] - gm);
        tot = fmaf(P[49], sc2, tot);
        av  = fmaf(P[d],  sc2, av);
    }
    float att = av / tot;
    g_pred[(q*NPREDD + iter)*48 + d] = att;
    float c = g_q[q*48+d] + att;
    sc[d] = c;
    __syncthreads();
    float qn = bq[d];
    const float* w = Wq + d*48;
    #pragma unroll 8
    for (int k = 0; k < 48; k++) qn = fmaf(sc[k], w[k], qn);
    g_q[q*48+d] = qn;
}

// ---------- decoder: GRU(96) x 12, block = 16 rows, 288 threads ----------
__global__ void __launch_bounds__(288) dec_kernel(
    const float* __restrict__ obs,
    const float* __restrict__ bih, const float* __restrict__ bhh,
    const float* __restrict__ fcw, const float* __restrict__ fcb,
    float* __restrict__ out)
{
    __shared__ float xh[96*16];
    __shared__ float ghs[288*16];
    int tid = threadIdx.x;
    int nbase = blockIdx.x*16;

    for (int i = tid; i < 96*16; i += 288) {
        int k = i >> 4, r = i & 15;
        int n = nbase + r;
        xh[i] = (k < 48) ? g_state[(n/NPREDD)*48 + k] : g_pred[(long)n*48 + (k-48)];
    }
    float pres = 0.f;
    if (tid < 32) {
        int n = nbase + (tid >> 1);
        pres = obs[(n/NPREDD)*16 + 14 + (tid & 1)];
    }
    __syncthreads();

    for (int t = 0; t < FUTD; t++) {
        const float* W  = (t == 0) ? g_wTih : g_wThh;
        const float* b0 = (t == 0) ? bih : bhh;
        const float* b1 = (t == 0) ? bhh : bih;
        float acc[16];
        float bb = b0[tid];
        #pragma unroll
        for (int r = 0; r < 16; r++) acc[r] = bb;
        #pragma unroll 4
        for (int k = 0; k < 96; k++) {
            float wv = W[k*288 + tid];
            float4 a0 = *(const float4*)&xh[k*16 + 0];
            float4 a1 = *(const float4*)&xh[k*16 + 4];
            float4 a2 = *(const float4*)&xh[k*16 + 8];
            float4 a3 = *(const float4*)&xh[k*16 + 12];
            acc[0]=fmaf(a0.x,wv,acc[0]);  acc[1]=fmaf(a0.y,wv,acc[1]);
            acc[2]=fmaf(a0.z,wv,acc[2]);  acc[3]=fmaf(a0.w,wv,acc[3]);
            acc[4]=fmaf(a1.x,wv,acc[4]);  acc[5]=fmaf(a1.y,wv,acc[5]);
            acc[6]=fmaf(a1.z,wv,acc[6]);  acc[7]=fmaf(a1.w,wv,acc[7]);
            acc[8]=fmaf(a2.x,wv,acc[8]);  acc[9]=fmaf(a2.y,wv,acc[9]);
            acc[10]=fmaf(a2.z,wv,acc[10]); acc[11]=fmaf(a2.w,wv,acc[11]);
            acc[12]=fmaf(a3.x,wv,acc[12]); acc[13]=fmaf(a3.y,wv,acc[13]);
            acc[14]=fmaf(a3.z,wv,acc[14]); acc[15]=fmaf(a3.w,wv,acc[15]);
        }
        __syncthreads();
        #pragma unroll
        for (int r4 = 0; r4 < 4; r4++)
            *(float4*)&ghs[tid*16 + r4*4] =
                make_float4(acc[r4*4], acc[r4*4+1], acc[r4*4+2], acc[r4*4+3]);
        __syncthreads();

        for (int i = tid; i < 96*16; i += 288) {
            int d = i >> 4, r = i & 15;
            float gr = ghs[d*16 + r];
            float gz = ghs[(96+d)*16 + r];
            float gn = ghs[(192+d)*16 + r];
            float rg = sg_(gr + b1[d]);
            float z  = sg_(gz + b1[96+d]);
            float nn;
            float h;
            if (t == 0) {
                nn = tanhf(gn + rg*b1[192+d]);
                h = (1.f - z)*nn;
            } else {
                nn = tanhf(b1[192+d] + rg*gn);
                h = (1.f - z)*nn + z*xh[d*16 + r];
            }
            xh[d*16 + r] = h;
        }
        __syncthreads();

        if (tid < 32) {
            int r = tid >> 1, c = tid & 1;
            const float* fw = fcw + c*96;
            float s = fcb[c];
            #pragma unroll 8
            for (int d = 0; d < 96; d++) s = fmaf(xh[d*16 + r], fw[d], s);
            pres += s;
            long n = nbase + r;
            out[(n*FUTD + t)*2 + c] = pres;
        }
    }
}

extern "C" void kernel_launch(void* const* d_in, const int* in_sizes, int n_in,
                              void* d_out, int out_size)
{
    const float* past    = (const float*)d_in[0];
    const float* obs     = (const float*)d_in[1];
    const float* conv_w  = (const float*)d_in[2];
    const float* conv_b  = (const float*)d_in[3];
    const float* enc_wih = (const float*)d_in[4];
    const float* enc_whh = (const float*)d_in[5];
    const float* enc_bih = (const float*)d_in[6];
    const float* enc_bhh = (const float*)d_in[7];
    const float* mem_p   = (const float*)d_in[8];
    const float* mem_f   = (const float*)d_in[9];
    const float* Wq      = (const float*)d_in[10];
    const float* bq      = (const float*)d_in[11];
    const float* Wk      = (const float*)d_in[12];
    const float* bk      = (const float*)d_in[13];
    const float* Wv      = (const float*)d_in[14];
    const float* bv      = (const float*)d_in[15];
    const float* dec_wih = (const float*)d_in[16];
    const float* dec_whh = (const float*)d_in[17];
    const float* dec_bih = (const float*)d_in[18];
    const float* dec_bhh = (const float*)d_in[19];
    const float* fc_w    = (const float*)d_in[20];
    const float* fc_b    = (const float*)d_in[21];
    float* out = (float*)d_out;

    enc_kernel<<<BD, 144>>>(past, conv_w, conv_b, enc_wih, enc_whh,
                            enc_bih, enc_bhh, Wq, bq);
    kv_kernel<<<(MD*48 + 255)/256, 256>>>(mem_p, mem_f, Wk, bk, Wv, bv);
    wt_kernel<<<(288*96 + 255)/256, 256>>>(dec_wih, dec_whh);

    for (int it = 0; it < NPREDD; it++) {
        attn_kernel<<<dim3(NSLICE, 16), 512>>>();
        combine_kernel<<<BD, 48>>>(Wq, bq, it);
    }

    dec_kernel<<<NROWS/16, 288>>>(obs, dec_bih, dec_bhh, fc_w, fc_b, out);
}

// round 4
// speedup vs baseline: 1.0311x; 1.0311x over previous
#include <cuda_runtime.h>
#include <math.h>

#define BD 512
#define MD 32768
#define NPREDD 20
#define FUTD 12
#define NROWS (BD*NPREDD)
#define NSLICE 9
#define SLICE_LEN 3641
#define QPB 16                      // queries per attention CTA
#define CH_F (64*52)                // floats per K (or V) chunk buffer
#define SMEM_ATTN ((QPB*48 + 4*CH_F)*4)

__device__ float g_state[BD*48];
__device__ float g_q[BD*48];
__device__ float g_K[MD*48];
__device__ float g_V[MD*48];
__device__ float g_part[NSLICE*BD*52];
__device__ float g_pred[NROWS*48];
__device__ float g_wTih[96*288];
__device__ float g_wThh[96*288];

__device__ __forceinline__ float sg_(float x){ return 1.f/(1.f+__expf(-x)); }

__device__ __forceinline__ void cpa16(void* dst, const void* src){
    unsigned ds = (unsigned)__cvta_generic_to_shared(dst);
    asm volatile("cp.async.cg.shared.global [%0], [%1], 16;\n" :: "r"(ds), "l"(src));
}

// ---------- encoder: conv1d(2,48,3,p=1)+ReLU, GRU(48) x8, q0 ----------
__global__ void enc_kernel(const float* __restrict__ past,
    const float* __restrict__ cw, const float* __restrict__ cb,
    const float* __restrict__ wih, const float* __restrict__ whh,
    const float* __restrict__ bih, const float* __restrict__ bhh,
    const float* __restrict__ Wq, const float* __restrict__ bq)
{
    __shared__ float se[8][48];
    __shared__ float sh[48];
    __shared__ float sgi[144], sgh[144];
    int b = blockIdx.x, tid = threadIdx.x;
    for (int idx = tid; idx < 8*48; idx += 144) {
        int t = idx/48, c = idx%48;
        float s = cb[c];
        #pragma unroll
        for (int k = 0; k < 3; k++) {
            int tt = t + k - 1;
            if (tt >= 0 && tt < 8) {
                s = fmaf(cw[c*6+k],   past[b*16+tt*2+0], s);
                s = fmaf(cw[c*6+3+k], past[b*16+tt*2+1], s);
            }
        }
        se[t][c] = fmaxf(s, 0.f);
    }
    if (tid < 48) sh[tid] = 0.f;
    __syncthreads();
    for (int t = 0; t < 8; t++) {
        float gi = bih[tid], gh = bhh[tid];
        const float* wi = wih + tid*48;
        const float* wh = whh + tid*48;
        #pragma unroll 8
        for (int d = 0; d < 48; d++) {
            gi = fmaf(se[t][d], wi[d], gi);
            gh = fmaf(sh[d],    wh[d], gh);
        }
        sgi[tid] = gi; sgh[tid] = gh;
        __syncthreads();
        float hn = 0.f;
        if (tid < 48) {
            float r = sg_(sgi[tid]    + sgh[tid]);
            float z = sg_(sgi[48+tid] + sgh[48+tid]);
            float n = tanhf(sgi[96+tid] + r*sgh[96+tid]);
            hn = (1.f-z)*n + z*sh[tid];
        }
        __syncthreads();
        if (tid < 48) sh[tid] = hn;
        __syncthreads();
    }
    if (tid < 48) {
        g_state[b*48+tid] = sh[tid];
        float q = bq[tid];
        const float* w = Wq + tid*48;
        #pragma unroll 8
        for (int d = 0; d < 48; d++) q = fmaf(sh[d], w[d], q);
        g_q[b*48+tid] = q;
    }
}

// ---------- K/V projection ----------
__global__ void kv_kernel(const float* __restrict__ mp, const float* __restrict__ mf,
    const float* __restrict__ Wk, const float* __restrict__ bk,
    const float* __restrict__ Wv, const float* __restrict__ bv)
{
    int idx = blockIdx.x*blockDim.x + threadIdx.x;
    if (idx >= MD*48) return;
    int m = idx/48, j = idx - m*48;
    const float* rp = mp + m*48;
    const float* rf = mf + m*48;
    const float* wk = Wk + j*48;
    const float* wv = Wv + j*48;
    float sk = bk[j], sv = bv[j];
    #pragma unroll 8
    for (int d = 0; d < 48; d++) {
        sk = fmaf(rp[d], wk[d], sk);
        sv = fmaf(rf[d], wv[d], sv);
    }
    g_K[idx] = sk;
    g_V[idx] = sv;
}

// ---------- decoder weight transpose ----------
__global__ void wt_kernel(const float* __restrict__ wih, const float* __restrict__ whh)
{
    int i = blockIdx.x*blockDim.x + threadIdx.x;
    if (i < 288*96) {
        int j = i/96, k = i - j*96;
        g_wTih[k*288+j] = wih[i];
        g_wThh[k*288+j] = whh[i];
    }
}

// ---------- attention partials: flash split-M, cp.async double buffer ----------
__global__ void __launch_bounds__(256,2) attn_kernel()
{
    extern __shared__ float sm[];
    float* sq  = sm;                 // QPB*48
    float* sKb = sm + QPB*48;        // 2 * CH_F
    float* sVb = sKb + 2*CH_F;       // 2 * CH_F

    int tid = threadIdx.x, lane = tid & 31, w = tid >> 5;
    int qbase = blockIdx.y * QPB;
    int m_start = blockIdx.x * SLICE_LEN;
    int m_end = min(MD, m_start + SLICE_LEN);
    int nchunks = (m_end - m_start + 63) >> 6;

    for (int i = tid; i < QPB*48; i += 256) sq[i] = g_q[qbase*48 + i];

    // prefetch chunk 0
    {
        int rows0 = min(64, m_end - m_start);
        const float4* gK4 = (const float4*)g_K + (size_t)m_start*12;
        const float4* gV4 = (const float4*)g_V + (size_t)m_start*12;
        for (int i = tid; i < rows0*12; i += 256) {
            int r = i/12, d4 = i - r*12;
            cpa16(sKb + r*52 + d4*4, gK4 + i);
            cpa16(sVb + r*52 + d4*4, gV4 + i);
        }
        asm volatile("cp.async.commit_group;\n");
    }

    float acc0[48], acc1[48];
    #pragma unroll
    for (int d = 0; d < 48; d++) { acc0[d] = 0.f; acc1[d] = 0.f; }
    float rm0 = -1e30f, rm1 = -1e30f, sum0 = 0.f, sum1 = 0.f;
    int q0 = w*2, q1 = q0 + 1;
    const float4* q4a = (const float4*)sq + q0*12;
    const float4* q4b = (const float4*)sq + q1*12;

    for (int c = 0; c < nchunks; c++) {
        asm volatile("cp.async.wait_group 0;\n" ::: "memory");
        __syncthreads();

        if (c + 1 < nchunks) {
            int m1 = m_start + (c+1)*64;
            int rows1 = min(64, m_end - m1);
            float* dK = sKb + ((c+1)&1)*CH_F;
            float* dV = sVb + ((c+1)&1)*CH_F;
            const float4* gK4 = (const float4*)g_K + (size_t)m1*12;
            const float4* gV4 = (const float4*)g_V + (size_t)m1*12;
            for (int i = tid; i < rows1*12; i += 256) {
                int r = i/12, d4 = i - r*12;
                cpa16(dK + r*52 + d4*4, gK4 + i);
                cpa16(dV + r*52 + d4*4, gV4 + i);
            }
        }
        asm volatile("cp.async.commit_group;\n");

        int rows = min(64, m_end - (m_start + c*64));
        const float4* k4a = (const float4*)(sKb + (c&1)*CH_F) + lane*13;
        const float4* k4b = k4a + 32*13;
        const float4* v4a = (const float4*)(sVb + (c&1)*CH_F) + lane*13;
        const float4* v4b = v4a + 32*13;

        float s00 = 0.f, s01 = 0.f, s10 = 0.f, s11 = 0.f;
        #pragma unroll
        for (int d4 = 0; d4 < 12; d4++) {
            float4 ka = k4a[d4], kb = k4b[d4];
            float4 qa = q4a[d4], qb = q4b[d4];
            s00 = fmaf(qa.x,ka.x,s00); s00 = fmaf(qa.y,ka.y,s00);
            s00 = fmaf(qa.z,ka.z,s00); s00 = fmaf(qa.w,ka.w,s00);
            s01 = fmaf(qa.x,kb.x,s01); s01 = fmaf(qa.y,kb.y,s01);
            s01 = fmaf(qa.z,kb.z,s01); s01 = fmaf(qa.w,kb.w,s01);
            s10 = fmaf(qb.x,ka.x,s10); s10 = fmaf(qb.y,ka.y,s10);
            s10 = fmaf(qb.z,ka.z,s10); s10 = fmaf(qb.w,ka.w,s10);
            s11 = fmaf(qb.x,kb.x,s11); s11 = fmaf(qb.y,kb.y,s11);
            s11 = fmaf(qb.z,kb.z,s11); s11 = fmaf(qb.w,kb.w,s11);
        }
        if (lane      >= rows) { s00 = -1e30f; s10 = -1e30f; }
        if (lane + 32 >= rows) { s01 = -1e30f; s11 = -1e30f; }

        // warp-uniform running max -> rescale is a rare uniform branch
        float m0l = fmaxf(s00, s01), m1l = fmaxf(s10, s11);
        #pragma unroll
        for (int off = 16; off; off >>= 1) {
            m0l = fmaxf(m0l, __shfl_xor_sync(0xffffffffu, m0l, off));
            m1l = fmaxf(m1l, __shfl_xor_sync(0xffffffffu, m1l, off));
        }
        if (m0l > rm0) {
            float f = __expf(rm0 - m0l);
            sum0 *= f;
            #pragma unroll
            for (int d = 0; d < 48; d++) acc0[d] *= f;
            rm0 = m0l;
        }
        if (m1l > rm1) {
            float f = __expf(rm1 - m1l);
            sum1 *= f;
            #pragma unroll
            for (int d = 0; d < 48; d++) acc1[d] *= f;
            rm1 = m1l;
        }
        float p00 = __expf(s00 - rm0), p01 = __expf(s01 - rm0);
        float p10 = __expf(s10 - rm1), p11 = __expf(s11 - rm1);
        sum0 += p00 + p01; sum1 += p10 + p11;

        #pragma unroll
        for (int d4 = 0; d4 < 12; d4++) {
            float4 va = v4a[d4], vb = v4b[d4];
            int d = d4*4;
            acc0[d+0] = fmaf(p00, va.x, acc0[d+0]);
            acc0[d+1] = fmaf(p00, va.y, acc0[d+1]);
            acc0[d+2] = fmaf(p00, va.z, acc0[d+2]);
            acc0[d+3] = fmaf(p00, va.w, acc0[d+3]);
            acc0[d+0] = fmaf(p01, vb.x, acc0[d+0]);
            acc0[d+1] = fmaf(p01, vb.y, acc0[d+1]);
            acc0[d+2] = fmaf(p01, vb.z, acc0[d+2]);
            acc0[d+3] = fmaf(p01, vb.w, acc0[d+3]);
            acc1[d+0] = fmaf(p10, va.x, acc1[d+0]);
            acc1[d+1] = fmaf(p10, va.y, acc1[d+1]);
            acc1[d+2] = fmaf(p10, va.z, acc1[d+2]);
            acc1[d+3] = fmaf(p10, va.w, acc1[d+3]);
            acc1[d+0] = fmaf(p11, vb.x, acc1[d+0]);
            acc1[d+1] = fmaf(p11, vb.y, acc1[d+1]);
            acc1[d+2] = fmaf(p11, vb.z, acc1[d+2]);
            acc1[d+3] = fmaf(p11, vb.w, acc1[d+3]);
        }
    }

    // cross-lane reduce (max already warp-uniform)
    #pragma unroll
    for (int off = 16; off; off >>= 1) {
        sum0 += __shfl_xor_sync(0xffffffffu, sum0, off);
        sum1 += __shfl_xor_sync(0xffffffffu, sum1, off);
        #pragma unroll
        for (int d = 0; d < 48; d++) {
            acc0[d] += __shfl_xor_sync(0xffffffffu, acc0[d], off);
            acc1[d] += __shfl_xor_sync(0xffffffffu, acc1[d], off);
        }
    }

    long s = blockIdx.x;
    if (lane == 0) {
        float* P = g_part + (s*BD + (qbase+q0))*52;
        #pragma unroll
        for (int d = 0; d < 48; d++) P[d] = acc0[d];
        P[48] = rm0; P[49] = sum0;
    }
    if (lane == 1) {
        float* P = g_part + (s*BD + (qbase+q1))*52;
        #pragma unroll
        for (int d = 0; d < 48; d++) P[d] = acc1[d];
        P[48] = rm1; P[49] = sum1;
    }
}

// ---------- combine partials + emit pred + next q ----------
__global__ void combine_kernel(const float* __restrict__ Wq, const float* __restrict__ bq,
                               int iter)
{
    __shared__ float sc[48];
    int q = blockIdx.x, d = threadIdx.x;
    float gm = -1e30f;
    #pragma unroll
    for (int s = 0; s < NSLICE; s++)
        gm = fmaxf(gm, g_part[((long)s*BD+q)*52 + 48]);
    float tot = 0.f, av = 0.f;
    #pragma unroll
    for (int s = 0; s < NSLICE; s++) {
        const float* P = g_part + ((long)s*BD+q)*52;
        float sc2 = __expf(P[48] - gm);
        tot = fmaf(P[49], sc2, tot);
        av  = fmaf(P[d],  sc2, av);
    }
    float att = av / tot;
    g_pred[(q*NPREDD + iter)*48 + d] = att;
    float c = g_q[q*48+d] + att;
    sc[d] = c;
    __syncthreads();
    float qn = bq[d];
    const float* w = Wq + d*48;
    #pragma unroll 8
    for (int k = 0; k < 48; k++) qn = fmaf(sc[k], w[k], qn);
    g_q[q*48+d] = qn;
}

// ---------- decoder: GRU(96) x 12, block = 16 rows, 288 threads ----------
__global__ void __launch_bounds__(288) dec_kernel(
    const float* __restrict__ obs,
    const float* __restrict__ bih, const float* __restrict__ bhh,
    const float* __restrict__ fcw, const float* __restrict__ fcb,
    float* __restrict__ out)
{
    __shared__ float xh[96*16];
    __shared__ float ghs[288*16];
    int tid = threadIdx.x;
    int nbase = blockIdx.x*16;

    for (int i = tid; i < 96*16; i += 288) {
        int k = i >> 4, r = i & 15;
        int n = nbase + r;
        xh[i] = (k < 48) ? g_state[(n/NPREDD)*48 + k] : g_pred[(long)n*48 + (k-48)];
    }
    float pres = 0.f;
    if (tid < 32) {
        int n = nbase + (tid >> 1);
        pres = obs[(n/NPREDD)*16 + 14 + (tid & 1)];
    }
    __syncthreads();

    for (int t = 0; t < FUTD; t++) {
        const float* W  = (t == 0) ? g_wTih : g_wThh;
        const float* b0 = (t == 0) ? bih : bhh;
        const float* b1 = (t == 0) ? bhh : bih;
        float acc[16];
        float bb = b0[tid];
        #pragma unroll
        for (int r = 0; r < 16; r++) acc[r] = bb;
        #pragma unroll 4
        for (int k = 0; k < 96; k++) {
            float wv = W[k*288 + tid];
            float4 a0 = *(const float4*)&xh[k*16 + 0];
            float4 a1 = *(const float4*)&xh[k*16 + 4];
            float4 a2 = *(const float4*)&xh[k*16 + 8];
            float4 a3 = *(const float4*)&xh[k*16 + 12];
            acc[0]=fmaf(a0.x,wv,acc[0]);  acc[1]=fmaf(a0.y,wv,acc[1]);
            acc[2]=fmaf(a0.z,wv,acc[2]);  acc[3]=fmaf(a0.w,wv,acc[3]);
            acc[4]=fmaf(a1.x,wv,acc[4]);  acc[5]=fmaf(a1.y,wv,acc[5]);
            acc[6]=fmaf(a1.z,wv,acc[6]);  acc[7]=fmaf(a1.w,wv,acc[7]);
            acc[8]=fmaf(a2.x,wv,acc[8]);  acc[9]=fmaf(a2.y,wv,acc[9]);
            acc[10]=fmaf(a2.z,wv,acc[10]); acc[11]=fmaf(a2.w,wv,acc[11]);
            acc[12]=fmaf(a3.x,wv,acc[12]); acc[13]=fmaf(a3.y,wv,acc[13]);
            acc[14]=fmaf(a3.z,wv,acc[14]); acc[15]=fmaf(a3.w,wv,acc[15]);
        }
        __syncthreads();
        #pragma unroll
        for (int r4 = 0; r4 < 4; r4++)
            *(float4*)&ghs[tid*16 + r4*4] =
                make_float4(acc[r4*4], acc[r4*4+1], acc[r4*4+2], acc[r4*4+3]);
        __syncthreads();

        for (int i = tid; i < 96*16; i += 288) {
            int d = i >> 4, r = i & 15;
            float gr = ghs[d*16 + r];
            float gz = ghs[(96+d)*16 + r];
            float gn = ghs[(192+d)*16 + r];
            float rg = sg_(gr + b1[d]);
            float z  = sg_(gz + b1[96+d]);
            float nn;
            float h;
            if (t == 0) {
                nn = tanhf(gn + rg*b1[192+d]);
                h = (1.f - z)*nn;
            } else {
                nn = tanhf(b1[192+d] + rg*gn);
                h = (1.f - z)*nn + z*xh[d*16 + r];
            }
            xh[d*16 + r] = h;
        }
        __syncthreads();

        if (tid < 32) {
            int r = tid >> 1, c = tid & 1;
            const float* fw = fcw + c*96;
            float s = fcb[c];
            #pragma unroll 8
            for (int d = 0; d < 96; d++) s = fmaf(xh[d*16 + r], fw[d], s);
            pres += s;
            long n = nbase + r;
            out[(n*FUTD + t)*2 + c] = pres;
        }
    }
}

extern "C" void kernel_launch(void* const* d_in, const int* in_sizes, int n_in,
                              void* d_out, int out_size)
{
    const float* past    = (const float*)d_in[0];
    const float* obs     = (const float*)d_in[1];
    const float* conv_w  = (const float*)d_in[2];
    const float* conv_b  = (const float*)d_in[3];
    const float* enc_wih = (const float*)d_in[4];
    const float* enc_whh = (const float*)d_in[5];
    const float* enc_bih = (const float*)d_in[6];
    const float* enc_bhh = (const float*)d_in[7];
    const float* mem_p   = (const float*)d_in[8];
    const float* mem_f   = (const float*)d_in[9];
    const float* Wq      = (const float*)d_in[10];
    const float* bq      = (const float*)d_in[11];
    const float* Wk      = (const float*)d_in[12];
    const float* bk      = (const float*)d_in[13];
    const float* Wv      = (const float*)d_in[14];
    const float* bv      = (const float*)d_in[15];
    const float* dec_wih = (const float*)d_in[16];
    const float* dec_whh = (const float*)d_in[17];
    const float* dec_bih = (const float*)d_in[18];
    const float* dec_bhh = (const float*)d_in[19];
    const float* fc_w    = (const float*)d_in[20];
    const float* fc_b    = (const float*)d_in[21];
    float* out = (float*)d_out;

    cudaFuncSetAttribute(attn_kernel,
        cudaFuncAttributeMaxDynamicSharedMemorySize, SMEM_ATTN);

    enc_kernel<<<BD, 144>>>(past, conv_w, conv_b, enc_wih, enc_whh,
                            enc_bih, enc_bhh, Wq, bq);
    kv_kernel<<<(MD*48 + 255)/256, 256>>>(mem_p, mem_f, Wk, bk, Wv, bv);
    wt_kernel<<<(288*96 + 255)/256, 256>>>(dec_wih, dec_whh);

    for (int it = 0; it < NPREDD; it++) {
        attn_kernel<<<dim3(NSLICE, BD/QPB), 256, SMEM_ATTN>>>();
        combine_kernel<<<BD, 48>>>(Wq, bq, it);
    }

    dec_kernel<<<NROWS/16, 288>>>(obs, dec_bih, dec_bhh, fc_w, fc_b, out);
}

// round 5
// speedup vs baseline: 1.9910x; 1.9309x over previous
#include <cuda_runtime.h>
#include <cuda_bf16.h>
#include <math.h>

#define BD 512
#define MD 32768
#define NPREDD 20
#define FUTD 12
#define NROWS (BD*NPREDD)
#define NSLICE 18

// ---- attention smem layout (bytes) ----
// buf b (b=0,1) at b*28160:
//   Kh [64][56] bf16 : +0     (7168 B)
//   Kl [64][56] bf16 : +7168
//   Vth [48][72] bf16: +14336 (6912 B)
//   Vtl [48][72] bf16: +21248
#define KVBUF_B   28160
#define OFF_Q     56320   // qh [32][56] bf16 (3584), ql (3584)
#define OFF_S     63488   // S [32][68] f32 (8704)
#define OFF_P     72192   // Ph [32][72] bf16 (4608), Pl (4608)
#define OFF_STAT  81408   // rm[32], rs[32], f[32] f32
#define SMEM_ATTN 81920

__device__ float g_state[BD*48];
__device__ float g_q[BD*48];
__device__ __nv_bfloat16 g_Kh[MD*48];
__device__ __nv_bfloat16 g_Kl[MD*48];
__device__ __nv_bfloat16 g_Vth[48*MD];
__device__ __nv_bfloat16 g_Vtl[48*MD];
__device__ float g_part[NSLICE*BD*52];
__device__ float g_pred[NROWS*48];
__device__ float g_wTih[96*288];
__device__ float g_wThh[96*288];

__device__ __forceinline__ float sg_(float x){ return 1.f/(1.f+__expf(-x)); }

__device__ __forceinline__ void cpa16(void* dst, const void* src){
    unsigned ds = (unsigned)__cvta_generic_to_shared(dst);
    asm volatile("cp.async.cg.shared.global [%0], [%1], 16;\n" :: "r"(ds), "l"(src));
}

#define MMA_BF16(c, a0,a1,a2,a3, b0,b1) \
    asm volatile("mma.sync.aligned.m16n8k16.row.col.f32.bf16.bf16.f32 " \
        "{%0,%1,%2,%3}, {%4,%5,%6,%7}, {%8,%9}, {%0,%1,%2,%3};" \
        : "+f"(c[0]), "+f"(c[1]), "+f"(c[2]), "+f"(c[3]) \
        : "r"(a0),"r"(a1),"r"(a2),"r"(a3),"r"(b0),"r"(b1))

__device__ __forceinline__ unsigned ldu32(const __nv_bfloat16* p){
    return *(const unsigned*)p;
}

// ---------- encoder: conv1d(2,48,3,p=1)+ReLU, GRU(48) x8, q0 ----------
__global__ void enc_kernel(const float* __restrict__ past,
    const float* __restrict__ cw, const float* __restrict__ cb,
    const float* __restrict__ wih, const float* __restrict__ whh,
    const float* __restrict__ bih, const float* __restrict__ bhh,
    const float* __restrict__ Wq, const float* __restrict__ bq)
{
    __shared__ float se[8][48];
    __shared__ float sh[48];
    __shared__ float sgi[144], sgh[144];
    int b = blockIdx.x, tid = threadIdx.x;
    for (int idx = tid; idx < 8*48; idx += 144) {
        int t = idx/48, c = idx%48;
        float s = cb[c];
        #pragma unroll
        for (int k = 0; k < 3; k++) {
            int tt = t + k - 1;
            if (tt >= 0 && tt < 8) {
                s = fmaf(cw[c*6+k],   past[b*16+tt*2+0], s);
                s = fmaf(cw[c*6+3+k], past[b*16+tt*2+1], s);
            }
        }
        se[t][c] = fmaxf(s, 0.f);
    }
    if (tid < 48) sh[tid] = 0.f;
    __syncthreads();
    for (int t = 0; t < 8; t++) {
        float gi = bih[tid], gh = bhh[tid];
        const float* wi = wih + tid*48;
        const float* wh = whh + tid*48;
        #pragma unroll 8
        for (int d = 0; d < 48; d++) {
            gi = fmaf(se[t][d], wi[d], gi);
            gh = fmaf(sh[d],    wh[d], gh);
        }
        sgi[tid] = gi; sgh[tid] = gh;
        __syncthreads();
        float hn = 0.f;
        if (tid < 48) {
            float r = sg_(sgi[tid]    + sgh[tid]);
            float z = sg_(sgi[48+tid] + sgh[48+tid]);
            float n = tanhf(sgi[96+tid] + r*sgh[96+tid]);
            hn = (1.f-z)*n + z*sh[tid];
        }
        __syncthreads();
        if (tid < 48) sh[tid] = hn;
        __syncthreads();
    }
    if (tid < 48) {
        g_state[b*48+tid] = sh[tid];
        float q = bq[tid];
        const float* w = Wq + tid*48;
        #pragma unroll 8
        for (int d = 0; d < 48; d++) q = fmaf(sh[d], w[d], q);
        g_q[b*48+tid] = q;
    }
}

// ---------- K projection + hi/lo split (m-major) ----------
__global__ void kproj_kernel(const float* __restrict__ mp,
    const float* __restrict__ Wk, const float* __restrict__ bk)
{
    int idx = blockIdx.x*blockDim.x + threadIdx.x;
    if (idx >= MD*48) return;
    int m = idx/48, j = idx - m*48;
    const float* rp = mp + m*48;
    const float* wk = Wk + j*48;
    float sk = bk[j];
    #pragma unroll 8
    for (int d = 0; d < 48; d++) sk = fmaf(rp[d], wk[d], sk);
    __nv_bfloat16 h = __float2bfloat16(sk);
    g_Kh[idx] = h;
    g_Kl[idx] = __float2bfloat16(sk - __bfloat162float(h));
}

// ---------- V projection + hi/lo split, TRANSPOSED (d-major) ----------
__global__ void vproj_kernel(const float* __restrict__ mf,
    const float* __restrict__ Wv, const float* __restrict__ bv)
{
    __shared__ float sW[48*48];
    __shared__ float sb[48];
    int tid = threadIdx.x;
    for (int i = tid; i < 48*48; i += 256) sW[i] = Wv[i];
    if (tid < 48) sb[tid] = bv[tid];
    __syncthreads();
    int m = blockIdx.x*256 + tid;
    float r[48];
    #pragma unroll 8
    for (int d = 0; d < 48; d++) r[d] = mf[(size_t)m*48 + d];
    #pragma unroll 1
    for (int j = 0; j < 48; j++) {
        float sv = sb[j];
        const float* w = sW + j*48;
        #pragma unroll 8
        for (int d = 0; d < 48; d++) sv = fmaf(r[d], w[d], sv);
        __nv_bfloat16 h = __float2bfloat16(sv);
        g_Vth[(size_t)j*MD + m] = h;
        g_Vtl[(size_t)j*MD + m] = __float2bfloat16(sv - __bfloat162float(h));
    }
}

// ---------- decoder weight transpose ----------
__global__ void wt_kernel(const float* __restrict__ wih, const float* __restrict__ whh)
{
    int i = blockIdx.x*blockDim.x + threadIdx.x;
    if (i < 288*96) {
        int j = i/96, k = i - j*96;
        g_wTih[k*288+j] = wih[i];
        g_wThh[k*288+j] = whh[i];
    }
}

// ---------- attention: bf16-split HMMA flash, split-M ----------
__global__ void __launch_bounds__(256,2) attn_kernel()
{
    extern __shared__ char sm[];
    __nv_bfloat16* sQh = (__nv_bfloat16*)(sm + OFF_Q);
    __nv_bfloat16* sQl = sQh + 32*56;
    float* sS = (float*)(sm + OFF_S);
    __nv_bfloat16* sPh = (__nv_bfloat16*)(sm + OFF_P);
    __nv_bfloat16* sPl = sPh + 32*72;
    float* sRM = (float*)(sm + OFF_STAT);
    float* sRS = sRM + 32;
    float* sF  = sRS + 32;

    int tid = threadIdx.x, lane = tid & 31, w = tid >> 5;
    int gid = lane >> 2, tg = lane & 3;
    int qbase = blockIdx.y * 32;
    int s = blockIdx.x;
    int m_start = (s < 8) ? s*1856 : 14848 + (s-8)*1792;
    int nch = (s < 8) ? 29 : 28;

    // load + split q
    for (int i = tid; i < 32*48; i += 256) {
        int q = i/48, d = i - (i/48)*48;
        float v = g_q[(qbase+q)*48 + d];
        __nv_bfloat16 h = __float2bfloat16(v);
        sQh[q*56+d] = h;
        sQl[q*56+d] = __float2bfloat16(v - __bfloat162float(h));
    }
    if (tid < 32) { sRM[tid] = -1e30f; sRS[tid] = 0.f; }

    // prefetch chunk 0
    {
        int m0 = m_start;
        char* base = sm;
        for (int i = tid; i < 768; i += 256) {
            int arr = i / 384;
            int r = (i % 384) / 6, seg = i % 6;
            const char* src = (const char*)(arr ? g_Kl : g_Kh) + ((size_t)(m0+r)*48)*2 + seg*16;
            cpa16(base + arr*7168 + r*112 + seg*16, src);
        }
        for (int i = tid; i < 768; i += 256) {
            int arr = i / 384;
            int r = (i % 384) / 8, seg = i % 8;
            const char* src = (const char*)(arr ? g_Vtl : g_Vth) + ((size_t)r*MD + m0)*2 + seg*16;
            cpa16(base + 14336 + arr*6912 + r*144 + seg*16, src);
        }
        asm volatile("cp.async.commit_group;\n");
    }

    float O[6][4];
    #pragma unroll
    for (int dt = 0; dt < 6; dt++)
        #pragma unroll
        for (int k = 0; k < 4; k++) O[dt][k] = 0.f;

    int q0 = (w & 1) * 16;        // query half
    int msub = (w >> 1) * 16;     // m slab within chunk

    for (int c = 0; c < nch; c++) {
        asm volatile("cp.async.wait_group 0;\n" ::: "memory");
        __syncthreads();

        if (c + 1 < nch) {
            int m0 = m_start + (c+1)*64;
            char* base = sm + ((c+1)&1)*KVBUF_B;
            for (int i = tid; i < 768; i += 256) {
                int arr = i / 384;
                int r = (i % 384) / 6, seg = i % 6;
                const char* src = (const char*)(arr ? g_Kl : g_Kh) + ((size_t)(m0+r)*48)*2 + seg*16;
                cpa16(base + arr*7168 + r*112 + seg*16, src);
            }
            for (int i = tid; i < 768; i += 256) {
                int arr = i / 384;
                int r = (i % 384) / 8, seg = i % 8;
                const char* src = (const char*)(arr ? g_Vtl : g_Vth) + ((size_t)r*MD + m0)*2 + seg*16;
                cpa16(base + 14336 + arr*6912 + r*144 + seg*16, src);
            }
        }
        asm volatile("cp.async.commit_group;\n");

        const __nv_bfloat16* Kh = (const __nv_bfloat16*)(sm + (c&1)*KVBUF_B);
        const __nv_bfloat16* Kl = Kh + 64*56;
        const __nv_bfloat16* Vh = (const __nv_bfloat16*)(sm + (c&1)*KVBUF_B + 14336);
        const __nv_bfloat16* Vl = Vh + 48*72;

        // ---- QK^T: S[32q x 64m], warp does q0..q0+15 x msub..msub+15 ----
        float Sf0[4] = {0.f,0.f,0.f,0.f};
        float Sf1[4] = {0.f,0.f,0.f,0.f};
        #pragma unroll
        for (int kc = 0; kc < 48; kc += 16) {
            const __nv_bfloat16* qr0 = sQh + (q0+gid)*56 + kc + tg*2;
            const __nv_bfloat16* qr1 = sQl + (q0+gid)*56 + kc + tg*2;
            unsigned qh0 = ldu32(qr0),        qh1 = ldu32(qr0 + 8*56);
            unsigned qh2 = ldu32(qr0 + 8),    qh3 = ldu32(qr0 + 8*56 + 8);
            unsigned ql0 = ldu32(qr1),        ql1 = ldu32(qr1 + 8*56);
            unsigned ql2 = ldu32(qr1 + 8),    ql3 = ldu32(qr1 + 8*56 + 8);
            #pragma unroll
            for (int nt = 0; nt < 2; nt++) {
                int mb = msub + nt*8 + gid;
                unsigned kh0 = ldu32(Kh + mb*56 + kc + tg*2);
                unsigned kh1 = ldu32(Kh + mb*56 + kc + tg*2 + 8);
                unsigned kl0 = ldu32(Kl + mb*56 + kc + tg*2);
                unsigned kl1 = ldu32(Kl + mb*56 + kc + tg*2 + 8);
                float* Sf = nt ? Sf1 : Sf0;
                MMA_BF16(Sf, qh0,qh1,qh2,qh3, kh0,kh1);
                MMA_BF16(Sf, qh0,qh1,qh2,qh3, kl0,kl1);
                MMA_BF16(Sf, ql0,ql1,ql2,ql3, kh0,kh1);
            }
        }
        // store S
        {
            float* p0 = sS + (q0+gid)*68 + msub + tg*2;
            float* p1 = sS + (q0+gid+8)*68 + msub + tg*2;
            p0[0] = Sf0[0]; p0[1] = Sf0[1];
            p1[0] = Sf0[2]; p1[1] = Sf0[3];
            p0[8] = Sf1[0]; p0[9] = Sf1[1];
            p1[8] = Sf1[2]; p1[9] = Sf1[3];
        }
        __syncthreads();

        // ---- online softmax over the 64-m chunk ----
        {
            int qq = tid >> 3, jj = tid & 7;
            const float* Srow = sS + qq*68 + jj*8;
            float v[8];
            #pragma unroll
            for (int k = 0; k < 8; k++) v[k] = Srow[k];
            float lm = v[0];
            #pragma unroll
            for (int k = 1; k < 8; k++) lm = fmaxf(lm, v[k]);
            #pragma unroll
            for (int off = 1; off < 8; off <<= 1)
                lm = fmaxf(lm, __shfl_xor_sync(0xffffffffu, lm, off));
            float oldm = sRM[qq];
            float newm = fmaxf(oldm, lm);
            float psum = 0.f;
            unsigned uh[4], ul[4];
            #pragma unroll
            for (int k = 0; k < 8; k += 2) {
                float pa = __expf(v[k]   - newm);
                float pb = __expf(v[k+1] - newm);
                psum += pa + pb;
                __nv_bfloat16 ha = __float2bfloat16(pa);
                __nv_bfloat16 hb = __float2bfloat16(pb);
                __nv_bfloat16 la = __float2bfloat16(pa - __bfloat162float(ha));
                __nv_bfloat16 lb = __float2bfloat16(pb - __bfloat162float(hb));
                uh[k>>1] = (unsigned)*(unsigned short*)&ha | ((unsigned)*(unsigned short*)&hb << 16);
                ul[k>>1] = (unsigned)*(unsigned short*)&la | ((unsigned)*(unsigned short*)&lb << 16);
            }
            *(uint4*)(sPh + qq*72 + jj*8) = make_uint4(uh[0],uh[1],uh[2],uh[3]);
            *(uint4*)(sPl + qq*72 + jj*8) = make_uint4(ul[0],ul[1],ul[2],ul[3]);
            #pragma unroll
            for (int off = 1; off < 8; off <<= 1)
                psum += __shfl_xor_sync(0xffffffffu, psum, off);
            if (jj == 0) {
                float f = __expf(oldm - newm);
                sF[qq] = f;
                sRM[qq] = newm;
                sRS[qq] = sRS[qq]*f + psum;
            }
        }
        __syncthreads();

        // ---- rescale O by f, then PV accumulate ----
        {
            float f0 = sF[q0 + gid], f1 = sF[q0 + gid + 8];
            #pragma unroll
            for (int dt = 0; dt < 6; dt++) {
                O[dt][0] *= f0; O[dt][1] *= f0;
                O[dt][2] *= f1; O[dt][3] *= f1;
            }
            const __nv_bfloat16* pr0 = sPh + (q0+gid)*72 + msub + tg*2;
            const __nv_bfloat16* pr1 = sPl + (q0+gid)*72 + msub + tg*2;
            unsigned ph0 = ldu32(pr0),     ph1 = ldu32(pr0 + 8*72);
            unsigned ph2 = ldu32(pr0 + 8), ph3 = ldu32(pr0 + 8*72 + 8);
            unsigned pl0 = ldu32(pr1),     pl1 = ldu32(pr1 + 8*72);
            unsigned pl2 = ldu32(pr1 + 8), pl3 = ldu32(pr1 + 8*72 + 8);
            #pragma unroll
            for (int dt = 0; dt < 6; dt++) {
                const __nv_bfloat16* vr = Vh + (dt*8+gid)*72 + msub + tg*2;
                const __nv_bfloat16* wr = Vl + (dt*8+gid)*72 + msub + tg*2;
                unsigned vh0 = ldu32(vr), vh1 = ldu32(vr + 8);
                unsigned vl0 = ldu32(wr), vl1 = ldu32(wr + 8);
                MMA_BF16(O[dt], ph0,ph1,ph2,ph3, vh0,vh1);
                MMA_BF16(O[dt], ph0,ph1,ph2,ph3, vl0,vl1);
                MMA_BF16(O[dt], pl0,pl1,pl2,pl3, vh0,vh1);
            }
        }
    }

    // ---- cross-warp O reduction (4 m-slab partials per q half) ----
    __syncthreads();
    float* Ored = (float*)sm;   // [2 halves][4 parts][16 q][48 d]
    {
        int half = w & 1, part = w >> 1;
        float* baseO = Ored + ((half*4 + part)*16)*48;
        #pragma unroll
        for (int dt = 0; dt < 6; dt++) {
            int col = dt*8 + tg*2;
            baseO[gid*48 + col]     = O[dt][0];
            baseO[gid*48 + col + 1] = O[dt][1];
            baseO[(gid+8)*48 + col]     = O[dt][2];
            baseO[(gid+8)*48 + col + 1] = O[dt][3];
        }
    }
    __syncthreads();
    for (int i = tid; i < 32*48; i += 256) {
        int q = i/48, d = i - (i/48)*48;
        int half = q >> 4, qq = q & 15;
        float sum = 0.f;
        #pragma unroll
        for (int part = 0; part < 4; part++)
            sum += Ored[((half*4 + part)*16 + qq)*48 + d];
        g_part[((size_t)s*BD + qbase + q)*52 + d] = sum;
    }
    if (tid < 32) {
        g_part[((size_t)s*BD + qbase + tid)*52 + 48] = sRM[tid];
        g_part[((size_t)s*BD + qbase + tid)*52 + 49] = sRS[tid];
    }
}

// ---------- combine partials + emit pred + next q ----------
__global__ void combine_kernel(const float* __restrict__ Wq, const float* __restrict__ bq,
                               int iter)
{
    __shared__ float sc[48];
    int q = blockIdx.x, d = threadIdx.x;
    float gm = -1e30f;
    #pragma unroll
    for (int s = 0; s < NSLICE; s++)
        gm = fmaxf(gm, g_part[((size_t)s*BD+q)*52 + 48]);
    float tot = 0.f, av = 0.f;
    #pragma unroll
    for (int s = 0; s < NSLICE; s++) {
        const float* P = g_part + ((size_t)s*BD+q)*52;
        float sc2 = __expf(P[48] - gm);
        tot = fmaf(P[49], sc2, tot);
        av  = fmaf(P[d],  sc2, av);
    }
    float att = av / tot;
    g_pred[(q*NPREDD + iter)*48 + d] = att;
    float c = g_q[q*48+d] + att;
    sc[d] = c;
    __syncthreads();
    float qn = bq[d];
    const float* w = Wq + d*48;
    #pragma unroll 8
    for (int k = 0; k < 48; k++) qn = fmaf(sc[k], w[k], qn);
    g_q[q*48+d] = qn;
}

// ---------- decoder: GRU(96) x 12, block = 16 rows, 288 threads ----------
__global__ void __launch_bounds__(288) dec_kernel(
    const float* __restrict__ obs,
    const float* __restrict__ bih, const float* __restrict__ bhh,
    const float* __restrict__ fcw, const float* __restrict__ fcb,
    float* __restrict__ out)
{
    __shared__ float xh[96*16];
    __shared__ float ghs[288*16];
    int tid = threadIdx.x;
    int nbase = blockIdx.x*16;

    for (int i = tid; i < 96*16; i += 288) {
        int k = i >> 4, r = i & 15;
        int n = nbase + r;
        xh[i] = (k < 48) ? g_state[(n/NPREDD)*48 + k] : g_pred[(size_t)n*48 + (k-48)];
    }
    float pres = 0.f;
    if (tid < 32) {
        int n = nbase + (tid >> 1);
        pres = obs[(n/NPREDD)*16 + 14 + (tid & 1)];
    }
    __syncthreads();

    for (int t = 0; t < FUTD; t++) {
        const float* W  = (t == 0) ? g_wTih : g_wThh;
        const float* b0 = (t == 0) ? bih : bhh;
        const float* b1 = (t == 0) ? bhh : bih;
        float acc[16];
        float bb = b0[tid];
        #pragma unroll
        for (int r = 0; r < 16; r++) acc[r] = bb;
        #pragma unroll 4
        for (int k = 0; k < 96; k++) {
            float wv = W[k*288 + tid];
            float4 a0 = *(const float4*)&xh[k*16 + 0];
            float4 a1 = *(const float4*)&xh[k*16 + 4];
            float4 a2 = *(const float4*)&xh[k*16 + 8];
            float4 a3 = *(const float4*)&xh[k*16 + 12];
            acc[0]=fmaf(a0.x,wv,acc[0]);  acc[1]=fmaf(a0.y,wv,acc[1]);
            acc[2]=fmaf(a0.z,wv,acc[2]);  acc[3]=fmaf(a0.w,wv,acc[3]);
            acc[4]=fmaf(a1.x,wv,acc[4]);  acc[5]=fmaf(a1.y,wv,acc[5]);
            acc[6]=fmaf(a1.z,wv,acc[6]);  acc[7]=fmaf(a1.w,wv,acc[7]);
            acc[8]=fmaf(a2.x,wv,acc[8]);  acc[9]=fmaf(a2.y,wv,acc[9]);
            acc[10]=fmaf(a2.z,wv,acc[10]); acc[11]=fmaf(a2.w,wv,acc[11]);
            acc[12]=fmaf(a3.x,wv,acc[12]); acc[13]=fmaf(a3.y,wv,acc[13]);
            acc[14]=fmaf(a3.z,wv,acc[14]); acc[15]=fmaf(a3.w,wv,acc[15]);
        }
        __syncthreads();
        #pragma unroll
        for (int r4 = 0; r4 < 4; r4++)
            *(float4*)&ghs[tid*16 + r4*4] =
                make_float4(acc[r4*4], acc[r4*4+1], acc[r4*4+2], acc[r4*4+3]);
        __syncthreads();

        for (int i = tid; i < 96*16; i += 288) {
            int d = i >> 4, r = i & 15;
            float gr = ghs[d*16 + r];
            float gz = ghs[(96+d)*16 + r];
            float gn = ghs[(192+d)*16 + r];
            float rg = sg_(gr + b1[d]);
            float z  = sg_(gz + b1[96+d]);
            float nn;
            float h;
            if (t == 0) {
                nn = tanhf(gn + rg*b1[192+d]);
                h = (1.f - z)*nn;
            } else {
                nn = tanhf(b1[192+d] + rg*gn);
                h = (1.f - z)*nn + z*xh[d*16 + r];
            }
            xh[d*16 + r] = h;
        }
        __syncthreads();

        if (tid < 32) {
            int r = tid >> 1, c = tid & 1;
            const float* fw = fcw + c*96;
            float s = fcb[c];
            #pragma unroll 8
            for (int d = 0; d < 96; d++) s = fmaf(xh[d*16 + r], fw[d], s);
            pres += s;
            size_t n = nbase + r;
            out[(n*FUTD + t)*2 + c] = pres;
        }
    }
}

extern "C" void kernel_launch(void* const* d_in, const int* in_sizes, int n_in,
                              void* d_out, int out_size)
{
    const float* past    = (const float*)d_in[0];
    const float* obs     = (const float*)d_in[1];
    const float* conv_w  = (const float*)d_in[2];
    const float* conv_b  = (const float*)d_in[3];
    const float* enc_wih = (const float*)d_in[4];
    const float* enc_whh = (const float*)d_in[5];
    const float* enc_bih = (const float*)d_in[6];
    const float* enc_bhh = (const float*)d_in[7];
    const float* mem_p   = (const float*)d_in[8];
    const float* mem_f   = (const float*)d_in[9];
    const float* Wq      = (const float*)d_in[10];
    const float* bq      = (const float*)d_in[11];
    const float* Wk      = (const float*)d_in[12];
    const float* bk      = (const float*)d_in[13];
    const float* Wv      = (const float*)d_in[14];
    const float* bv      = (const float*)d_in[15];
    const float* dec_wih = (const float*)d_in[16];
    const float* dec_whh = (const float*)d_in[17];
    const float* dec_bih = (const float*)d_in[18];
    const float* dec_bhh = (const float*)d_in[19];
    const float* fc_w    = (const float*)d_in[20];
    const float* fc_b    = (const float*)d_in[21];
    float* out = (float*)d_out;

    cudaFuncSetAttribute(attn_kernel,
        cudaFuncAttributeMaxDynamicSharedMemorySize, SMEM_ATTN);

    enc_kernel<<<BD, 144>>>(past, conv_w, conv_b, enc_wih, enc_whh,
                            enc_bih, enc_bhh, Wq, bq);
    kproj_kernel<<<(MD*48 + 255)/256, 256>>>(mem_p, Wk, bk);
    vproj_kernel<<<MD/256, 256>>>(mem_f, Wv, bv);
    wt_kernel<<<(288*96 + 255)/256, 256>>>(dec_wih, dec_whh);

    for (int it = 0; it < NPREDD; it++) {
        attn_kernel<<<dim3(NSLICE, BD/32), 256, SMEM_ATTN>>>();
        combine_kernel<<<BD, 48>>>(Wq, bq, it);
    }

    dec_kernel<<<NROWS/16, 288>>>(obs, dec_bih, dec_bhh, fc_w, fc_b, out);
}